// round 4
// baseline (speedup 1.0000x reference)
#include <cuda_runtime.h>

#define B_    16
#define N_    2048
#define D_    1024
#define KH    15
#define KL    5
#define ROWS  320      // B_*KH + B_*KL
#define HROWS 240      // B_*KH
#define SPLITK 8
#define KC    (D_ / SPLITK)   // 128
#define GRID_ 320
#define NTHR  256

#define BM 64
#define BN 64
#define BK 16

// ---------------- scratch (no allocations allowed) ----------------
__device__ unsigned int g_pmax[B_];
__device__ unsigned int g_pmin[B_];
__device__ float        g_psum[B_];
__device__ int          g_idx[ROWS];
__device__ int          g_val[ROWS];
__device__ int          g_lab[ROWS];
__device__ __align__(16) float g_Gk[SPLITK][ROWS * ROWS];
__device__ float        g_per[ROWS];
__device__ int          g_bar[4];
__device__ int          g_fin;

// ---------------- helpers ----------------
__device__ __forceinline__ unsigned long long u64min(unsigned long long a,
                                                     unsigned long long b) {
    return a < b ? a : b;
}

__device__ __forceinline__ unsigned long long f32x2_fma(unsigned long long c,
                                                        unsigned long long a,
                                                        unsigned long long b) {
    asm("fma.rn.f32x2 %0, %1, %2, %0;" : "+l"(c) : "l"(a), "l"(b));
    return c;
}

__device__ __forceinline__ unsigned long long dup_f32(float x) {
    unsigned long long r;
    unsigned u = __float_as_uint(x);
    asm("mov.b64 %0, {%1, %1};" : "=l"(r) : "r"(u));
    return r;
}

__device__ __forceinline__ int ld_cg(const int* p) {
    int v;
    asm volatile("ld.global.cg.b32 %0, [%1];" : "=r"(v) : "l"(p));
    return v;
}

// grid-wide barrier: all GRID_ blocks co-resident by construction
__device__ __forceinline__ void gsync(int ph) {
    __syncthreads();
    if (threadIdx.x == 0) {
        __threadfence();
        atomicAdd(&g_bar[ph], 1);
        while (ld_cg(&g_bar[ph]) < GRID_) { __nanosleep(32); }
        __threadfence();
    }
    __syncthreads();
}

// ---------------- fused kernel ----------------
__global__ void __launch_bounds__(NTHR, 3)
k_fused(const float* __restrict__ fea, const float* __restrict__ score,
        const int* __restrict__ label, const float* __restrict__ t_logit,
        const float* __restrict__ ori, const float* __restrict__ l2w,
        float* __restrict__ out) {
    __shared__ __align__(16) unsigned char SMEM[2 * BK * (BM + 2) * 4];
    int bid = blockIdx.x, tid = threadIdx.x;
    int lane = tid & 31, warp = tid >> 5;

    // ================= Phase A: per-bag min/max/sum (blocks 0-15) ==========
    if (bid < B_) {
        unsigned* smx = (unsigned*)SMEM;          // [8]
        unsigned* smn = smx + 8;                  // [8]
        float*    ssm = (float*)(smn + 8);        // [8]
        int b = bid;
        unsigned mx = 0u, mn = 0xFFFFFFFFu;
        float s = 0.f;
#pragma unroll
        for (int i = 0; i < 8; i++) {
            float v = score[b * N_ + tid + i * 256];
            unsigned bb = __float_as_uint(v);     // score >= 0 -> bits monotonic
            mx = max(mx, bb);
            mn = min(mn, bb);
            s += v;
        }
#pragma unroll
        for (int o = 16; o; o >>= 1) {
            mx = max(mx, __shfl_down_sync(0xffffffffu, mx, o));
            mn = min(mn, __shfl_down_sync(0xffffffffu, mn, o));
            s += __shfl_down_sync(0xffffffffu, s, o);
        }
        if (lane == 0) { smx[warp] = mx; smn[warp] = mn; ssm[warp] = s; }
        __syncthreads();
        if (tid == 0) {
            for (int w = 1; w < 8; w++) {
                mx = max(mx, smx[w]); mn = min(mn, smn[w]); s += ssm[w];
            }
            g_pmax[b] = mx; g_pmin[b] = mn; g_psum[b] = s;
        }
    }
    gsync(0);

    // ================= Phase B: selection =================================
    // blocks 0-15: HIGH top-15 for bag bid; blocks 16-31: LOW for bag bid-16.
    // key = (score_bits << 32) | idx -> lexicographic (score, idx), matching
    // jnp stable ascending argsort (score >= 0).
    if (bid < 32) {
        unsigned long long* s_w = (unsigned long long*)SMEM;  // [2][8]
        bool isHigh = bid < B_;
        int b = isHigh ? bid : bid - B_;

        unsigned mxb = 0u, mnb = 0xFFFFFFFFu;
#pragma unroll
        for (int i = 0; i < B_; i++) {
            mxb = max(mxb, g_pmax[i]);
            mnb = min(mnb, g_pmin[i]);
        }
        float lo, hi;
        if (isHigh) { hi = __uint_as_float(mxb); lo = hi - 0.3f; }
        else        { lo = __uint_as_float(mnb); hi = lo + 1e-9f; }

        unsigned long long key[8];
#pragma unroll
        for (int i = 0; i < 8; i++) {
            float sc = score[b * N_ + tid + i * 256];
            key[i] = (sc >= lo && sc <= hi)
                ? (((unsigned long long)__float_as_uint(sc) << 32) |
                   (unsigned)(tid + i * 256))
                : ~0ULL;
        }
        unsigned long long loc = key[0];
#pragma unroll
        for (int i = 1; i < 8; i++) loc = u64min(loc, key[i]);

        int nrounds = isHigh ? KH : 10;
        int labb = isHigh ? label[b] : 2;
        unsigned long long sel[10];
        int par = 0;
        for (int t = 0; t < nrounds; t++) {
            unsigned long long m = loc;
#pragma unroll
            for (int o = 16; o; o >>= 1)
                m = u64min(m, __shfl_down_sync(0xffffffffu, m, o));
            if (lane == 0) s_w[par * 8 + warp] = m;
            __syncthreads();
            unsigned long long best = s_w[par * 8 + 0];
#pragma unroll
            for (int w = 1; w < 8; w++) best = u64min(best, s_w[par * 8 + w]);
            par ^= 1;
            if (loc == best && best != ~0ULL) {       // unique owner pops
#pragma unroll
                for (int i = 0; i < 8; i++) if (key[i] == best) key[i] = ~0ULL;
                loc = key[0];
#pragma unroll
                for (int i = 1; i < 8; i++) loc = u64min(loc, key[i]);
            }
            if (isHigh) {
                if (tid == 0) {
                    int r = b * KH + t;
                    if (best != ~0ULL) {
                        g_val[r] = 1;
                        g_idx[r] = b * N_ + (int)(best & 0xFFFFFFFFULL);
                    } else { g_val[r] = 0; g_idx[r] = 0; }
                    g_lab[r] = labb;
                }
            } else {
                sel[t] = best;
            }
        }
        if (!isHigh && tid == 0) {
            for (int j = 0; j < KL; j++) {           // even ranks 0,2,4,6,8
                unsigned long long k = sel[2 * j];
                int r = HROWS + b * KL + j;
                if (k != ~0ULL) {
                    g_val[r] = 1;
                    g_idx[r] = b * N_ + (int)(k & 0xFFFFFFFFULL);
                } else { g_val[r] = 0; g_idx[r] = 0; }
                g_lab[r] = 2;
            }
        }
    }
    gsync(1);

    // ================= Phase C: gram GEMM (blocks 0-199) ===================
    // G = X X^T, 320x320, K=1024 split into 8 slabs; gather fused via g_idx.
    if (bid < 25 * SPLITK) {
        float (*As)[BM + 2] = (float(*)[BM + 2])SMEM;
        float (*Bs)[BN + 2] = (float(*)[BN + 2])(SMEM + BK * (BM + 2) * 4);
        int kz = bid & 7, tile = bid >> 3;
        int bm = tile / 5, bn = tile % 5;
        int tx = tid & 15, ty = tid >> 4;
        int tx4 = tx * 4, ty4 = ty * 4;

        unsigned long long cc[4][2];
#pragma unroll
        for (int i = 0; i < 4; i++) { cc[i][0] = 0ULL; cc[i][1] = 0ULL; }

        int loadRow = tid >> 2;
        int loadK4  = (tid & 3) * 4;
        const float* A0 = fea + (size_t)g_idx[bm * BM + loadRow] * D_ + kz * KC;
        const float* B0 = fea + (size_t)g_idx[bn * BN + loadRow] * D_ + kz * KC;

        for (int k0 = 0; k0 < KC; k0 += BK) {
            float4 a  = *(const float4*)(A0 + k0 + loadK4);
            float4 b4 = *(const float4*)(B0 + k0 + loadK4);
            As[loadK4 + 0][loadRow] = a.x;
            As[loadK4 + 1][loadRow] = a.y;
            As[loadK4 + 2][loadRow] = a.z;
            As[loadK4 + 3][loadRow] = a.w;
            Bs[loadK4 + 0][loadRow] = b4.x;
            Bs[loadK4 + 1][loadRow] = b4.y;
            Bs[loadK4 + 2][loadRow] = b4.z;
            Bs[loadK4 + 3][loadRow] = b4.w;
            __syncthreads();
#pragma unroll
            for (int k = 0; k < BK; k++) {
                float2 a01 = *(const float2*)&As[k][ty4];
                float2 a23 = *(const float2*)&As[k][ty4 + 2];
                unsigned long long bp0 = *(const unsigned long long*)&Bs[k][tx4];
                unsigned long long bp1 = *(const unsigned long long*)&Bs[k][tx4 + 2];
                unsigned long long A0d = dup_f32(a01.x);
                unsigned long long A1d = dup_f32(a01.y);
                unsigned long long A2d = dup_f32(a23.x);
                unsigned long long A3d = dup_f32(a23.y);
                cc[0][0] = f32x2_fma(cc[0][0], A0d, bp0);
                cc[0][1] = f32x2_fma(cc[0][1], A0d, bp1);
                cc[1][0] = f32x2_fma(cc[1][0], A1d, bp0);
                cc[1][1] = f32x2_fma(cc[1][1], A1d, bp1);
                cc[2][0] = f32x2_fma(cc[2][0], A2d, bp0);
                cc[2][1] = f32x2_fma(cc[2][1], A2d, bp1);
                cc[3][0] = f32x2_fma(cc[3][0], A3d, bp0);
                cc[3][1] = f32x2_fma(cc[3][1], A3d, bp1);
            }
            __syncthreads();
        }

        float* og = g_Gk[kz];
#pragma unroll
        for (int i = 0; i < 4; i++) {
            unsigned lo0, hi0, lo1, hi1;
            asm("mov.b64 {%0, %1}, %2;" : "=r"(lo0), "=r"(hi0) : "l"(cc[i][0]));
            asm("mov.b64 {%0, %1}, %2;" : "=r"(lo1), "=r"(hi1) : "l"(cc[i][1]));
            float4 v = make_float4(__uint_as_float(lo0), __uint_as_float(hi0),
                                   __uint_as_float(lo1), __uint_as_float(hi1));
            int row = bm * BM + ty4 + i;
            *(float4*)(og + (size_t)row * ROWS + bn * BN + tx4) = v;
        }
    }
    gsync(2);

    // ================= Phase D: per-query loss (all 320 blocks) ============
    {
        float* red = (float*)SMEM;      // [16]
        int q = bid;
        int labq = g_lab[q];
        float den = 0.f, num = 0.f;
        for (int n = tid; n < ROWS; n += NTHR) {
            float g = 0.f;
#pragma unroll
            for (int s = 0; s < SPLITK; s++) g += g_Gk[s][q * ROWS + n];
            float e = expf(g * 0.0625f);          // TAU = 16
            e = g_val[n] ? e : 0.f;
            den += e;
            if (g_lab[n] == labq) num += e;
        }
#pragma unroll
        for (int o = 16; o; o >>= 1) {
            den += __shfl_down_sync(0xffffffffu, den, o);
            num += __shfl_down_sync(0xffffffffu, num, o);
        }
        if (lane == 0) { red[warp] = den; red[8 + warp] = num; }
        __syncthreads();
        if (tid == 0) {
            float d = 0.f, nm = 0.f;
#pragma unroll
            for (int w = 0; w < 8; w++) { d += red[w]; nm += red[8 + w]; }
            g_per[q] = g_val[q] ? -logf(nm / d) : 0.f;
        }
    }
    gsync(3);

    // ================= final scalar (block 0) ==============================
    if (bid == 0 && tid == 0) {
        float contr = 0.f;
        for (int b = 0; b < B_; b++) {
            float s = 0.f; int c = 0;
            for (int k = 0; k < KH; k++) { int r = b * KH + k; s += g_per[r]; c += g_val[r]; }
            for (int k = 0; k < KL; k++) { int r = HROWS + b * KL + k; s += g_per[r]; c += g_val[r]; }
            contr += s / (float)c;
        }
        contr /= (float)B_;

        float t = t_logit[0];
        float ce = 0.f;
        for (int b = 0; b < B_; b++) {
            float se = expf(ori[b * 2 + 0]) + expf(ori[b * 2 + 1]);
            ce += -logf(expf(t) / se);
        }
        ce /= (float)B_;

        unsigned mx = 0u;
        float sum = 0.f;
        for (int i = 0; i < B_; i++) { mx = max(mx, g_pmax[i]); sum += g_psum[i]; }
        float gmax = __uint_as_float(mx);
        float meanv = sum / (float)(B_ * N_);
        float Dm = meanv / gmax;
        float l2 = 0.0001f * (1.f - Dm) * (1.f - Dm) * l2w[0];

        out[0] = contr + ce + l2;
    }

    // ================= reset barrier state for next graph replay ===========
    if (tid == 0) {
        __threadfence();
        int old = atomicAdd(&g_fin, 1);
        if (old == GRID_ - 1) {      // last block: nobody reads counters anymore
            g_bar[0] = 0; g_bar[1] = 0; g_bar[2] = 0; g_bar[3] = 0;
            g_fin = 0;
            __threadfence();
        }
    }
}

// ---------------- launch ----------------
extern "C" void kernel_launch(void* const* d_in, const int* in_sizes, int n_in,
                              void* d_out, int out_size) {
    const float* fea     = (const float*)d_in[0];
    const float* score   = (const float*)d_in[1];
    const int*   label   = (const int*)d_in[2];
    const float* t_logit = (const float*)d_in[3];
    const float* ori     = (const float*)d_in[4];
    const float* l2w     = (const float*)d_in[5];
    float* out = (float*)d_out;

    k_fused<<<GRID_, NTHR>>>(fea, score, label, t_logit, ori, l2w, out);
}

// round 5
// speedup vs baseline: 1.2597x; 1.2597x over previous
#include <cuda_runtime.h>

#define B_    16
#define N_    2048
#define D_    1024
#define KH    15
#define KL    5
#define ROWS  320      // B_*KH + B_*KL
#define HROWS 240      // B_*KH
#define SPLITK 8
#define KC    (D_ / SPLITK)   // 128

#define BM 64
#define BN 64
#define BK 16

// ---------------- scratch (no allocations allowed) ----------------
__device__ unsigned int g_pmax[B_];
__device__ unsigned int g_pmin[B_];
__device__ float        g_psum[B_];
__device__ int          g_idx[ROWS];
__device__ int          g_val[ROWS];
__device__ int          g_lab[ROWS];
__device__ __align__(16) float g_Gk[SPLITK][ROWS * ROWS];
__device__ float        g_per[ROWS];
__device__ int          g_bar1;   // 32-block barrier in k_selall
__device__ int          g_fin1;   // reset helper
__device__ int          g_cnt3;   // completion counter in k_loss

// ---------------- helpers ----------------
__device__ __forceinline__ unsigned long long u64min(unsigned long long a,
                                                     unsigned long long b) {
    return a < b ? a : b;
}

__device__ __forceinline__ unsigned long long f32x2_fma(unsigned long long c,
                                                        unsigned long long a,
                                                        unsigned long long b) {
    asm("fma.rn.f32x2 %0, %1, %2, %0;" : "+l"(c) : "l"(a), "l"(b));
    return c;
}

__device__ __forceinline__ unsigned long long dup_f32(float x) {
    unsigned long long r;
    unsigned u = __float_as_uint(x);
    asm("mov.b64 %0, {%1, %1};" : "=l"(r) : "r"(u));
    return r;
}

__device__ __forceinline__ int ld_cg(const int* p) {
    int v;
    asm volatile("ld.global.cg.b32 %0, [%1];" : "=r"(v) : "l"(p));
    return v;
}

// ================= K1: bag partials + selection (32 blocks) =================
// blocks 0-15: HIGH top-15 of bag bid; blocks 16-31: LOW picks of bag bid-16.
// key = (score_bits << 32) | idx -> lexicographic (score, idx), matching
// jnp stable ascending argsort (score >= 0).
__global__ void __launch_bounds__(256) k_selall(const float* __restrict__ score,
                                                const int* __restrict__ label) {
    __shared__ unsigned long long s_w[16];
    __shared__ unsigned s_mx[8], s_mn[8];
    __shared__ float s_sm[8];
    int bid = blockIdx.x, tid = threadIdx.x;
    int lane = tid & 31, warp = tid >> 5;
    bool isHigh = bid < B_;
    int b = isHigh ? bid : bid - B_;

    float sc[8];
#pragma unroll
    for (int i = 0; i < 8; i++) sc[i] = score[b * N_ + tid + i * 256];

    // ---- bag partials (HIGH blocks only, one per bag) ----
    if (isHigh) {
        unsigned mx = 0u, mn = 0xFFFFFFFFu;
        float s = 0.f;
#pragma unroll
        for (int i = 0; i < 8; i++) {
            unsigned bb = __float_as_uint(sc[i]);   // score >= 0 -> monotonic
            mx = max(mx, bb);
            mn = min(mn, bb);
            s += sc[i];
        }
#pragma unroll
        for (int o = 16; o; o >>= 1) {
            mx = max(mx, __shfl_down_sync(0xffffffffu, mx, o));
            mn = min(mn, __shfl_down_sync(0xffffffffu, mn, o));
            s += __shfl_down_sync(0xffffffffu, s, o);
        }
        if (lane == 0) { s_mx[warp] = mx; s_mn[warp] = mn; s_sm[warp] = s; }
        __syncthreads();
        if (tid == 0) {
            for (int w = 1; w < 8; w++) {
                mx = max(mx, s_mx[w]); mn = min(mn, s_mn[w]); s += s_sm[w];
            }
            g_pmax[b] = mx; g_pmin[b] = mn; g_psum[b] = s;
        }
    }

    // ---- grid sync over 32 blocks ----
    __syncthreads();
    if (tid == 0) {
        __threadfence();
        atomicAdd(&g_bar1, 1);
        while (ld_cg(&g_bar1) < 32) { __nanosleep(32); }
        __threadfence();
    }
    __syncthreads();

    // ---- global bounds ----
    unsigned mxb = 0u, mnb = 0xFFFFFFFFu;
#pragma unroll
    for (int i = 0; i < B_; i++) {
        mxb = max(mxb, g_pmax[i]);
        mnb = min(mnb, g_pmin[i]);
    }
    float lo, hi;
    if (isHigh) { hi = __uint_as_float(mxb); lo = hi - 0.3f; }
    else        { lo = __uint_as_float(mnb); hi = lo + 1e-9f; }

    unsigned long long key[8];
#pragma unroll
    for (int i = 0; i < 8; i++) {
        key[i] = (sc[i] >= lo && sc[i] <= hi)
            ? (((unsigned long long)__float_as_uint(sc[i]) << 32) |
               (unsigned)(tid + i * 256))
            : ~0ULL;
    }
    unsigned long long loc = key[0];
#pragma unroll
    for (int i = 1; i < 8; i++) loc = u64min(loc, key[i]);

    int nrounds = isHigh ? KH : 10;
    int labb = isHigh ? label[b] : 2;
    unsigned long long sel[10];
    for (int t = 0; t < nrounds; t++) {
        unsigned long long m = loc;
#pragma unroll
        for (int o = 16; o; o >>= 1)
            m = u64min(m, __shfl_down_sync(0xffffffffu, m, o));
        if (lane == 0) s_w[(t & 1) * 8 + warp] = m;
        __syncthreads();
        unsigned long long best = s_w[(t & 1) * 8 + 0];
#pragma unroll
        for (int w = 1; w < 8; w++) best = u64min(best, s_w[(t & 1) * 8 + w]);
        if (loc == best && best != ~0ULL) {         // unique owner pops
#pragma unroll
            for (int i = 0; i < 8; i++) if (key[i] == best) key[i] = ~0ULL;
            loc = key[0];
#pragma unroll
            for (int i = 1; i < 8; i++) loc = u64min(loc, key[i]);
        }
        if (isHigh) {
            if (tid == 0) {
                int r = b * KH + t;
                if (best != ~0ULL) {
                    g_val[r] = 1;
                    g_idx[r] = b * N_ + (int)(best & 0xFFFFFFFFULL);
                } else { g_val[r] = 0; g_idx[r] = 0; }
                g_lab[r] = labb;
            }
        } else {
            sel[t] = best;
        }
    }
    if (!isHigh && tid == 0) {
        for (int j = 0; j < KL; j++) {              // even ranks 0,2,4,6,8
            unsigned long long k = sel[2 * j];
            int r = HROWS + b * KL + j;
            if (k != ~0ULL) {
                g_val[r] = 1;
                g_idx[r] = b * N_ + (int)(k & 0xFFFFFFFFULL);
            } else { g_val[r] = 0; g_idx[r] = 0; }
            g_lab[r] = 2;  // N_CLASSES
        }
    }

    // ---- reset barrier state for next graph replay ----
    if (tid == 0) {
        int o = atomicAdd(&g_fin1, 1);
        if (o == 31) { g_bar1 = 0; g_fin1 = 0; __threadfence(); }
    }
}

// ===== K2: gram G = X X^T (320x320, K=1024), fused gather, double-buffered ===
__global__ void __launch_bounds__(256) k_gemm(const float* __restrict__ fea) {
    __shared__ __align__(16) float As[2][BK][BM + 2];
    __shared__ __align__(16) float Bs[2][BK][BN + 2];
    int kz = blockIdx.x & 7, tile = blockIdx.x >> 3;
    int bm = tile / 5, bn = tile % 5;
    int tid = threadIdx.x;
    int tx = tid & 15, ty = tid >> 4;
    int tx4 = tx * 4, ty4 = ty * 4;

    unsigned long long cc[4][2];
#pragma unroll
    for (int i = 0; i < 4; i++) { cc[i][0] = 0ULL; cc[i][1] = 0ULL; }

    int loadRow = tid >> 2;           // 0..63
    int loadK4  = (tid & 3) * 4;      // 0,4,8,12
    // indirect gather: invalid rows point at row 0; masked in k_loss
    const float* A0 = fea + (size_t)g_idx[bm * BM + loadRow] * D_ + kz * KC + loadK4;
    const float* B0 = fea + (size_t)g_idx[bn * BN + loadRow] * D_ + kz * KC + loadK4;

    float4 a = *(const float4*)A0;
    float4 b4 = *(const float4*)B0;
    As[0][loadK4 + 0][loadRow] = a.x;
    As[0][loadK4 + 1][loadRow] = a.y;
    As[0][loadK4 + 2][loadRow] = a.z;
    As[0][loadK4 + 3][loadRow] = a.w;
    Bs[0][loadK4 + 0][loadRow] = b4.x;
    Bs[0][loadK4 + 1][loadRow] = b4.y;
    Bs[0][loadK4 + 2][loadRow] = b4.z;
    Bs[0][loadK4 + 3][loadRow] = b4.w;
    __syncthreads();

#pragma unroll
    for (int it = 0; it < KC / BK; it++) {
        int cur = it & 1;
        if (it < KC / BK - 1) {                      // prefetch next slab
            a  = *(const float4*)(A0 + (it + 1) * BK);
            b4 = *(const float4*)(B0 + (it + 1) * BK);
        }
#pragma unroll
        for (int k = 0; k < BK; k++) {
            float2 a01 = *(const float2*)&As[cur][k][ty4];
            float2 a23 = *(const float2*)&As[cur][k][ty4 + 2];
            unsigned long long bp0 = *(const unsigned long long*)&Bs[cur][k][tx4];
            unsigned long long bp1 = *(const unsigned long long*)&Bs[cur][k][tx4 + 2];
            unsigned long long A0d = dup_f32(a01.x);
            unsigned long long A1d = dup_f32(a01.y);
            unsigned long long A2d = dup_f32(a23.x);
            unsigned long long A3d = dup_f32(a23.y);
            cc[0][0] = f32x2_fma(cc[0][0], A0d, bp0);
            cc[0][1] = f32x2_fma(cc[0][1], A0d, bp1);
            cc[1][0] = f32x2_fma(cc[1][0], A1d, bp0);
            cc[1][1] = f32x2_fma(cc[1][1], A1d, bp1);
            cc[2][0] = f32x2_fma(cc[2][0], A2d, bp0);
            cc[2][1] = f32x2_fma(cc[2][1], A2d, bp1);
            cc[3][0] = f32x2_fma(cc[3][0], A3d, bp0);
            cc[3][1] = f32x2_fma(cc[3][1], A3d, bp1);
        }
        if (it < KC / BK - 1) {
            int nxt = cur ^ 1;
            As[nxt][loadK4 + 0][loadRow] = a.x;
            As[nxt][loadK4 + 1][loadRow] = a.y;
            As[nxt][loadK4 + 2][loadRow] = a.z;
            As[nxt][loadK4 + 3][loadRow] = a.w;
            Bs[nxt][loadK4 + 0][loadRow] = b4.x;
            Bs[nxt][loadK4 + 1][loadRow] = b4.y;
            Bs[nxt][loadK4 + 2][loadRow] = b4.z;
            Bs[nxt][loadK4 + 3][loadRow] = b4.w;
            __syncthreads();
        }
    }

    float* og = g_Gk[kz];
#pragma unroll
    for (int i = 0; i < 4; i++) {
        unsigned lo0, hi0, lo1, hi1;
        asm("mov.b64 {%0, %1}, %2;" : "=r"(lo0), "=r"(hi0) : "l"(cc[i][0]));
        asm("mov.b64 {%0, %1}, %2;" : "=r"(lo1), "=r"(hi1) : "l"(cc[i][1]));
        float4 v = make_float4(__uint_as_float(lo0), __uint_as_float(hi0),
                               __uint_as_float(lo1), __uint_as_float(hi1));
        int row = bm * BM + ty4 + i;
        *(float4*)(og + (size_t)row * ROWS + bn * BN + tx4) = v;
    }
}

// ===== K3: per-query loss (320 blocks) + fused final scalar ==================
__global__ void __launch_bounds__(256) k_loss(const float* __restrict__ t_logit,
                                              const float* __restrict__ ori,
                                              const float* __restrict__ l2w,
                                              float* __restrict__ out) {
    __shared__ float red[16];
    __shared__ int s_last;
    __shared__ float s_c[B_], s_ce[B_];
    int q = blockIdx.x, tid = threadIdx.x;
    int lane = tid & 31, warp = tid >> 5;
    int labq = g_lab[q];
    float den = 0.f, num = 0.f;
    for (int n = tid; n < ROWS; n += 256) {
        float g = 0.f;
#pragma unroll
        for (int s = 0; s < SPLITK; s++) g += g_Gk[s][q * ROWS + n];
        float e = __expf(g * 0.0625f);              // TAU = 16
        e = g_val[n] ? e : 0.f;
        den += e;
        if (g_lab[n] == labq) num += e;
    }
#pragma unroll
    for (int o = 16; o; o >>= 1) {
        den += __shfl_down_sync(0xffffffffu, den, o);
        num += __shfl_down_sync(0xffffffffu, num, o);
    }
    if (lane == 0) { red[warp] = den; red[8 + warp] = num; }
    __syncthreads();
    if (tid == 0) {
        float d = 0.f, nm = 0.f;
#pragma unroll
        for (int w = 0; w < 8; w++) { d += red[w]; nm += red[8 + w]; }
        g_per[q] = g_val[q] ? -__logf(nm / d) : 0.f;
        __threadfence();
        int o = atomicAdd(&g_cnt3, 1);
        s_last = (o == ROWS - 1);
    }
    __syncthreads();

    if (s_last) {                                   // last block: final scalar
        __threadfence();
        if (tid < B_) {
            int b = tid;
            float s = 0.f; int c = 0;
            for (int k = 0; k < KH; k++) { int r = b * KH + k; s += g_per[r]; c += g_val[r]; }
            for (int k = 0; k < KL; k++) { int r = HROWS + b * KL + k; s += g_per[r]; c += g_val[r]; }
            s_c[b] = s / (float)c;
            float se = __expf(ori[b * 2 + 0]) + __expf(ori[b * 2 + 1]);
            s_ce[b] = -__logf(__expf(t_logit[0]) / se);
        }
        __syncthreads();
        if (tid == 0) {
            float contr = 0.f, ce = 0.f;
#pragma unroll
            for (int b = 0; b < B_; b++) { contr += s_c[b]; ce += s_ce[b]; }
            contr /= (float)B_;
            ce /= (float)B_;

            unsigned mx = 0u;
            float sum = 0.f;
#pragma unroll
            for (int i = 0; i < B_; i++) { mx = max(mx, g_pmax[i]); sum += g_psum[i]; }
            float gmax = __uint_as_float(mx);
            float meanv = sum / (float)(B_ * N_);
            float Dm = meanv / gmax;
            float l2 = 0.0001f * (1.f - Dm) * (1.f - Dm) * l2w[0];

            out[0] = contr + ce + l2;
            g_cnt3 = 0;                             // reset for next replay
            __threadfence();
        }
    }
}

// ---------------- launch ----------------
extern "C" void kernel_launch(void* const* d_in, const int* in_sizes, int n_in,
                              void* d_out, int out_size) {
    const float* fea     = (const float*)d_in[0];
    const float* score   = (const float*)d_in[1];
    const int*   label   = (const int*)d_in[2];
    const float* t_logit = (const float*)d_in[3];
    const float* ori     = (const float*)d_in[4];
    const float* l2w     = (const float*)d_in[5];
    float* out = (float*)d_out;

    k_selall<<<32, 256>>>(score, label);
    k_gemm<<<25 * SPLITK, 256>>>(fea);
    k_loss<<<ROWS, 256>>>(t_logit, ori, l2w, out);
}